// round 5
// baseline (speedup 1.0000x reference)
#include <cuda_runtime.h>
#include <cstdint>

#define NN 50000
#define NE 800000
#define IND 2613
#define HD  256

// ---------------- scratch (static device memory; no allocs) ----------------
__device__ float g_h[(size_t)NN * HD];   // GEMM output / messages (hs)
__device__ float g_x[(size_t)NN * HD];   // layer activations
__device__ float g_dinv[NN];
__device__ int   g_deg[NN];
__device__ int   g_cursor[NN];
__device__ int   g_rowptr[NN + 1];
__device__ int   g_srcs[NE];

// ============================ PTX helpers ============================
__device__ __forceinline__ uint32_t smem_u32(const void* p) {
    uint32_t a;
    asm("{ .reg .u64 t; cvta.to.shared.u64 t, %1; cvt.u32.u64 %0, t; }" : "=r"(a) : "l"(p));
    return a;
}
__device__ __forceinline__ void ldmx4(uint32_t* r, uint32_t addr) {
    asm volatile("ldmatrix.sync.aligned.m8n8.x4.shared.b16 {%0,%1,%2,%3}, [%4];"
                 : "=r"(r[0]), "=r"(r[1]), "=r"(r[2]), "=r"(r[3]) : "r"(addr));
}
__device__ __forceinline__ void mma_tf32(float* c, const uint32_t* a, const uint32_t* b) {
    asm volatile("mma.sync.aligned.m16n8k8.row.col.f32.tf32.tf32.f32 "
                 "{%0,%1,%2,%3}, {%4,%5,%6,%7}, {%8,%9}, {%0,%1,%2,%3};"
                 : "+f"(c[0]), "+f"(c[1]), "+f"(c[2]), "+f"(c[3])
                 : "r"(a[0]), "r"(a[1]), "r"(a[2]), "r"(a[3]), "r"(b[0]), "r"(b[1]));
}
__device__ __forceinline__ float totf32(float x) {
    uint32_t u;
    asm("cvt.rna.tf32.f32 %0, %1;" : "=r"(u) : "f"(x));
    return __uint_as_float(u);
}

// ============================ CSR build ============================
__global__ void k_zero() {
    int i = blockIdx.x * blockDim.x + threadIdx.x;
    if (i < NN) { g_deg[i] = 0; g_cursor[i] = 0; }
}
__global__ void k_histo(const int* __restrict__ dst) {
    int e = blockIdx.x * blockDim.x + threadIdx.x;
    if (e < NE) atomicAdd(&g_deg[dst[e]], 1);
}
__global__ void k_scan() {
    __shared__ int s[1024];
    __shared__ int carry_s;
    int tid = threadIdx.x;
    if (tid == 0) carry_s = 0;
    __syncthreads();
    for (int base = 0; base < NN; base += 1024) {
        int i = base + tid;
        int v = (i < NN) ? g_deg[i] : 0;
        if (i < NN) g_dinv[i] = rsqrtf((float)(v + 1));
        s[tid] = v;
        __syncthreads();
#pragma unroll
        for (int off = 1; off < 1024; off <<= 1) {
            int t = (tid >= off) ? s[tid - off] : 0;
            __syncthreads();
            s[tid] += t;
            __syncthreads();
        }
        int incl = s[tid];
        int carry = carry_s;
        if (i < NN) g_rowptr[i] = carry + incl - v;
        __syncthreads();
        if (tid == 1023) carry_s = carry + incl;
        __syncthreads();
    }
    if (tid == 0) g_rowptr[NN] = carry_s;
}
__global__ void k_scatter(const int* __restrict__ src, const int* __restrict__ dst) {
    int e = blockIdx.x * blockDim.x + threadIdx.x;
    if (e < NE) {
        int d = dst[e];
        int p = g_rowptr[d] + atomicAdd(&g_cursor[d], 1);
        g_srcs[p] = src[e];
    }
}

// ============================ TF32 GEMM ============================
// C[i,j] = sum_k A[i,k]*B[j,k]; A:[M,K] fp32 row-major, B:[256,K] fp32 row-major.
// tf32 mma m16n8k8, single term, inputs rounded with cvt.rna.
// CTA 128x256, 512 threads = 16 warps (4x4), warp tile 32x64.
// LDG->reg prefetch + STS, double-buffered smem (handles odd K!).
// EPI 0: C = acc * dinv[row] ; EPI 1: elu(acc+bias) ; EPI 2: acc+bias
#define BM 128
#define BN 256
#define BK 32
#define PR 36                                   // floats per padded smem row (144 B)
#define A_ST (BM * PR * 4)                      // 18432 B
#define B_ST (BN * PR * 4)                      // 36864 B
#define STG (A_ST + B_ST)                       // 55296 B
#define SM_TOTAL (2 * STG)                      // 110592 B

template <int EPI>
__global__ void __launch_bounds__(512, 1)
k_tgemm(const float* __restrict__ A, const float* __restrict__ B,
        const float* __restrict__ bias, float* __restrict__ C, int M, int K)
{
    extern __shared__ char sm[];
    const uint32_t sb = smem_u32(sm);
    const int tid  = threadIdx.x;
    const int lane = tid & 31;
    const int wid  = tid >> 5;
    const int wm   = wid >> 2;          // 0..3 (32 rows)
    const int wn   = wid & 3;           // 0..3 (64 cols)
    const int g    = lane >> 2;         // 0..7
    const int t    = lane & 3;          // 0..3
    const int bm   = blockIdx.x * BM;

    // fill mapping: chunk id -> (row, kc); 4 consecutive k per chunk
    const int ar0 = (tid + 0)   >> 3, ak0 = (tid & 7) << 2;          // A chunks
    const int ar1 = (tid + 512) >> 3;
    // B chunks: rows (tid+i*512)>>3, same kc pattern
    // ldmatrix lane mapping (validated in round 3)
    const uint32_t a_lrow = (uint32_t)(lane & 15);
    const uint32_t a_lkh  = (uint32_t)((lane >> 4) << 4);
    const uint32_t b_lrow = (uint32_t)((lane & 7) + ((lane >> 4) << 3));
    const uint32_t b_lkh  = (uint32_t)(((lane >> 3) & 1) << 4);

    float acc[2][8][4];
#pragma unroll
    for (int m = 0; m < 2; m++)
#pragma unroll
        for (int n = 0; n < 8; n++)
#pragma unroll
            for (int q = 0; q < 4; q++) acc[m][n][q] = 0.f;

    const int nt = (K + BK - 1) / BK;
    const bool vec = ((K & 3) == 0);
    float fa[8], fb[16];

    // ---- prefetch one stage into registers ----
    auto prefetch = [&](int kt) {
        const int k0 = kt * BK;
#pragma unroll
        for (int i = 0; i < 2; i++) {
            int row = (i == 0) ? ar0 : ar1;
            int gr  = bm + row;
            int kk  = k0 + ak0;
            const float* p = A + (size_t)gr * K + kk;
            if (gr < M && kk + 4 <= K) {
                if (vec) { float4 u = *(const float4*)p;
                    fa[i*4+0]=u.x; fa[i*4+1]=u.y; fa[i*4+2]=u.z; fa[i*4+3]=u.w; }
                else {
#pragma unroll
                    for (int j = 0; j < 4; j++) fa[i*4+j] = __ldg(p + j);
                }
            } else {
#pragma unroll
                for (int j = 0; j < 4; j++)
                    fa[i*4+j] = (gr < M && kk + j < K) ? __ldg(p + j) : 0.f;
            }
        }
#pragma unroll
        for (int i = 0; i < 4; i++) {
            int row = (tid + i * 512) >> 3;
            int kk  = k0 + ak0;
            const float* p = B + (size_t)row * K + kk;
            if (kk + 4 <= K) {
                if (vec) { float4 u = *(const float4*)p;
                    fb[i*4+0]=u.x; fb[i*4+1]=u.y; fb[i*4+2]=u.z; fb[i*4+3]=u.w; }
                else {
#pragma unroll
                    for (int j = 0; j < 4; j++) fb[i*4+j] = __ldg(p + j);
                }
            } else {
#pragma unroll
                for (int j = 0; j < 4; j++)
                    fb[i*4+j] = (kk + j < K) ? __ldg(p + j) : 0.f;
            }
        }
    };

    prefetch(0);

    for (int kt = 0; kt < nt; kt++) {
        const uint32_t stg = (uint32_t)(kt & 1) * STG;

        // ---- store prefetched tile (tf32-rounded) ----
#pragma unroll
        for (int i = 0; i < 2; i++) {
            int row = (i == 0) ? ar0 : ar1;
            *(float4*)(sm + stg + (uint32_t)(row * PR + ak0) * 4) =
                make_float4(totf32(fa[i*4]), totf32(fa[i*4+1]),
                            totf32(fa[i*4+2]), totf32(fa[i*4+3]));
        }
#pragma unroll
        for (int i = 0; i < 4; i++) {
            int row = (tid + i * 512) >> 3;
            *(float4*)(sm + stg + A_ST + (uint32_t)(row * PR + ak0) * 4) =
                make_float4(totf32(fb[i*4]), totf32(fb[i*4+1]),
                            totf32(fb[i*4+2]), totf32(fb[i*4+3]));
        }
        __syncthreads();

        if (kt + 1 < nt) prefetch(kt + 1);

        // ---- fragments + MMA: 4 k-steps of 8 ----
#pragma unroll
        for (int s = 0; s < 4; s++) {
            uint32_t a[2][4], b[4][4];
#pragma unroll
            for (int mt = 0; mt < 2; mt++) {
                uint32_t R = (uint32_t)(wm * 32 + mt * 16) + a_lrow;
                ldmx4(a[mt], sb + stg + R * 144 + (uint32_t)(s * 32) + a_lkh);
            }
#pragma unroll
            for (int np = 0; np < 4; np++) {
                uint32_t Cb = (uint32_t)(wn * 64 + np * 16) + b_lrow;
                ldmx4(b[np], sb + stg + (uint32_t)A_ST + Cb * 144 + (uint32_t)(s * 32) + b_lkh);
            }
#pragma unroll
            for (int mt = 0; mt < 2; mt++)
#pragma unroll
                for (int np = 0; np < 4; np++) {
                    mma_tf32(acc[mt][np * 2 + 0], a[mt], &b[np][0]);
                    mma_tf32(acc[mt][np * 2 + 1], a[mt], &b[np][2]);
                }
        }
        __syncthreads();
    }

    // ---- epilogue ----
#pragma unroll
    for (int mt = 0; mt < 2; mt++) {
        int r0 = bm + wm * 32 + mt * 16 + g;
        int r1 = r0 + 8;
        float dv0 = 0.f, dv1 = 0.f;
        if (EPI == 0) {
            if (r0 < M) dv0 = g_dinv[r0];
            if (r1 < M) dv1 = g_dinv[r1];
        }
#pragma unroll
        for (int nf = 0; nf < 8; nf++) {
            int col = wn * 64 + nf * 8 + t * 2;
            float b0 = 0.f, b1 = 0.f;
            if (EPI != 0) { b0 = __ldg(bias + col); b1 = __ldg(bias + col + 1); }
            float* c = acc[mt][nf];
            float v0 = c[0], v1 = c[1], v2 = c[2], v3 = c[3];
            if (EPI == 0) { v0 *= dv0; v1 *= dv0; v2 *= dv1; v3 *= dv1; }
            else {
                v0 += b0; v1 += b1; v2 += b0; v3 += b1;
                if (EPI == 1) {
                    v0 = (v0 > 0.f) ? v0 : expm1f(v0);
                    v1 = (v1 > 0.f) ? v1 : expm1f(v1);
                    v2 = (v2 > 0.f) ? v2 : expm1f(v2);
                    v3 = (v3 > 0.f) ? v3 : expm1f(v3);
                }
            }
            if (r0 < M) *(float2*)(C + (size_t)r0 * BN + col) = make_float2(v0, v1);
            if (r1 < M) *(float2*)(C + (size_t)r1 * BN + col) = make_float2(v2, v3);
        }
    }
}

// ============================ aggregation ============================
// out[v] = l2norm( relu( dinv[v]*(sum_{u->v} hs[u] + hs[v]) + bias ) )
__global__ void __launch_bounds__(HD)
k_agg(const float* __restrict__ hs, const float* __restrict__ bias,
      float* __restrict__ outx)
{
    int v = blockIdx.x;
    int j = threadIdx.x;

    float s = hs[(size_t)v * HD + j];
    int beg = g_rowptr[v], end = g_rowptr[v + 1];
    for (int e = beg; e < end; e++) {
        int u = g_srcs[e];
        s += hs[(size_t)u * HD + j];
    }
    float val = fmaf(g_dinv[v], s, bias[j]);
    val = fmaxf(val, 0.f);

    __shared__ float red[8];
    float ss = val * val;
#pragma unroll
    for (int o = 16; o; o >>= 1) ss += __shfl_xor_sync(0xffffffffu, ss, o);
    if ((j & 31) == 0) red[j >> 5] = ss;
    __syncthreads();
    if (j < 8) {
        float t = red[j];
#pragma unroll
        for (int o = 4; o; o >>= 1) t += __shfl_xor_sync(0xffu, t, o);
        if (j == 0) red[0] = t;
    }
    __syncthreads();
    float scale = 1.f / fmaxf(sqrtf(red[0]), 1e-12f);
    outx[(size_t)v * HD + j] = val * scale;
}

// ============================ launch ============================
extern "C" void kernel_launch(void* const* d_in, const int* in_sizes, int n_in,
                              void* d_out, int out_size)
{
    const float* x     = (const float*)d_in[0];
    const int*   edges = (const int*)  d_in[1];
    const float* Wg0   = (const float*)d_in[2];
    const float* bg0   = (const float*)d_in[3];
    const float* Wg1   = (const float*)d_in[4];
    const float* bg1   = (const float*)d_in[5];
    const float* Wg2   = (const float*)d_in[6];
    const float* bg2   = (const float*)d_in[7];
    const float* W1    = (const float*)d_in[8];
    const float* b1    = (const float*)d_in[9];
    const float* W2    = (const float*)d_in[10];
    const float* b2    = (const float*)d_in[11];
    float* out = (float*)d_out;

    const int* src = edges;
    const int* dst = edges + NE;

    float *hp, *xp;
    cudaGetSymbolAddress((void**)&hp, g_h);
    cudaGetSymbolAddress((void**)&xp, g_x);

    cudaFuncSetAttribute(k_tgemm<0>, cudaFuncAttributeMaxDynamicSharedMemorySize, SM_TOTAL);
    cudaFuncSetAttribute(k_tgemm<1>, cudaFuncAttributeMaxDynamicSharedMemorySize, SM_TOTAL);
    cudaFuncSetAttribute(k_tgemm<2>, cudaFuncAttributeMaxDynamicSharedMemorySize, SM_TOTAL);

    // CSR build + dinv
    k_zero   <<<(NN + 255) / 256, 256>>>();
    k_histo  <<<(NE + 255) / 256, 256>>>(dst);
    k_scan   <<<1, 1024>>>();
    k_scatter<<<(NE + 255) / 256, 256>>>(src, dst);

    const int grd = (NN + BM - 1) / BM;   // 391

    // GCN layer 0 (K = 2613)
    k_tgemm<0><<<grd, 512, SM_TOTAL>>>(x,  Wg0, nullptr, hp, NN, IND);
    k_agg     <<<NN, HD>>>(hp, bg0, xp);
    // GCN layer 1
    k_tgemm<0><<<grd, 512, SM_TOTAL>>>(xp, Wg1, nullptr, hp, NN, HD);
    k_agg     <<<NN, HD>>>(hp, bg1, xp);
    // GCN layer 2
    k_tgemm<0><<<grd, 512, SM_TOTAL>>>(xp, Wg2, nullptr, hp, NN, HD);
    k_agg     <<<NN, HD>>>(hp, bg2, xp);
    // MLP
    k_tgemm<1><<<grd, 512, SM_TOTAL>>>(xp, W1, b1, hp,  NN, HD);
    k_tgemm<2><<<grd, 512, SM_TOTAL>>>(hp, W2, b2, out, NN, HD);
}

// round 6
// speedup vs baseline: 1.3120x; 1.3120x over previous
#include <cuda_runtime.h>
#include <cuda_fp16.h>
#include <cstdint>

#define NN 50000
#define NE 800000
#define IND 2613
#define HD  256

// ---------------- scratch (static device memory; no allocs) ----------------
__device__ float g_h[(size_t)NN * HD];   // GEMM output / messages (hs)
__device__ float g_x[(size_t)NN * HD];   // layer activations
__device__ float g_dinv[NN];
__device__ int   g_deg[NN];
__device__ int   g_cursor[NN];
__device__ int   g_rowptr[NN + 1];
__device__ int   g_srcs[NE];

// ============================ PTX helpers ============================
__device__ __forceinline__ uint32_t smem_u32(const void* p) {
    uint32_t a;
    asm("{ .reg .u64 t; cvta.to.shared.u64 t, %1; cvt.u32.u64 %0, t; }" : "=r"(a) : "l"(p));
    return a;
}
__device__ __forceinline__ void ldmx4(uint32_t* r, uint32_t addr) {
    asm volatile("ldmatrix.sync.aligned.m8n8.x4.shared.b16 {%0,%1,%2,%3}, [%4];"
                 : "=r"(r[0]), "=r"(r[1]), "=r"(r[2]), "=r"(r[3]) : "r"(addr));
}
__device__ __forceinline__ void mma_f16(float* c, const uint32_t* a, const uint32_t* b) {
    asm volatile("mma.sync.aligned.m16n8k16.row.col.f32.f16.f16.f32 "
                 "{%0,%1,%2,%3}, {%4,%5,%6,%7}, {%8,%9}, {%0,%1,%2,%3};"
                 : "+f"(c[0]), "+f"(c[1]), "+f"(c[2]), "+f"(c[3])
                 : "r"(a[0]), "r"(a[1]), "r"(a[2]), "r"(a[3]), "r"(b[0]), "r"(b[1]));
}
// A-side: 4 fp32 -> 4 fp16 hi + 4 fp16 lo (residual)
__device__ __forceinline__ void cvt4a(const float* f, uint2& hi, uint2& lo) {
    __half2 h0 = __float22half2_rn(make_float2(f[0], f[1]));
    __half2 h1 = __float22half2_rn(make_float2(f[2], f[3]));
    float r0 = f[0] - __low2float(h0);
    float r1 = f[1] - __high2float(h0);
    float r2 = f[2] - __low2float(h1);
    float r3 = f[3] - __high2float(h1);
    __half2 l0 = __float22half2_rn(make_float2(r0, r1));
    __half2 l1 = __float22half2_rn(make_float2(r2, r3));
    hi = make_uint2(*(uint32_t*)&h0, *(uint32_t*)&h1);
    lo = make_uint2(*(uint32_t*)&l0, *(uint32_t*)&l1);
}
// B-side: 4 fp32 -> 4 fp16 (single rounding)
__device__ __forceinline__ void cvt4b(const float* f, uint2& hi) {
    __half2 h0 = __float22half2_rn(make_float2(f[0], f[1]));
    __half2 h1 = __float22half2_rn(make_float2(f[2], f[3]));
    hi = make_uint2(*(uint32_t*)&h0, *(uint32_t*)&h1);
}

// ============================ CSR build ============================
__global__ void k_zero() {
    int i = blockIdx.x * blockDim.x + threadIdx.x;
    if (i < NN) { g_deg[i] = 0; g_cursor[i] = 0; }
}
__global__ void k_histo(const int* __restrict__ dst) {
    int e = blockIdx.x * blockDim.x + threadIdx.x;
    if (e < NE) atomicAdd(&g_deg[dst[e]], 1);
}
__global__ void k_scan() {
    __shared__ int s[1024];
    __shared__ int carry_s;
    int tid = threadIdx.x;
    if (tid == 0) carry_s = 0;
    __syncthreads();
    for (int base = 0; base < NN; base += 1024) {
        int i = base + tid;
        int v = (i < NN) ? g_deg[i] : 0;
        if (i < NN) g_dinv[i] = rsqrtf((float)(v + 1));
        s[tid] = v;
        __syncthreads();
#pragma unroll
        for (int off = 1; off < 1024; off <<= 1) {
            int t = (tid >= off) ? s[tid - off] : 0;
            __syncthreads();
            s[tid] += t;
            __syncthreads();
        }
        int incl = s[tid];
        int carry = carry_s;
        if (i < NN) g_rowptr[i] = carry + incl - v;
        __syncthreads();
        if (tid == 1023) carry_s = carry + incl;
        __syncthreads();
    }
    if (tid == 0) g_rowptr[NN] = carry_s;
}
__global__ void k_scatter(const int* __restrict__ src, const int* __restrict__ dst) {
    int e = blockIdx.x * blockDim.x + threadIdx.x;
    if (e < NE) {
        int d = dst[e];
        int p = g_rowptr[d] + atomicAdd(&g_cursor[d], 1);
        g_srcs[p] = src[e];
    }
}

// ============================ fp16 split-A GEMM ============================
// C[i,j] = sum_k A[i,k]*B[j,k]; A:[M,K] fp32 row-major, B:[256,K] fp32 row-major.
// A = Ah + Al (fp16 pair, exact to ~2^-22); B ~= Bh (fp16, rounds at 2^-12).
// acc += Ah*Bh + Al*Bh  (= A * Bh exactly), fp32 accumulate -> rel err ~1e-4.
// CTA: 128(M) x 256(N), 512 threads, 16 warps (4x4), warp tile 32x64.
// EPI 0: C = acc * dinv[row] ; EPI 1: elu(acc+bias) ; EPI 2: acc+bias
#define BM 128
#define BN 256
#define BK 16
#define SROW 48                      // bytes per smem row (16 fp16 + 8 pad)
#define AH_OFF 0
#define AL_OFF (128 * SROW)          // 6144
#define BH_OFF (2 * 128 * SROW)      // 12288
#define STG_BYTES (BH_OFF + 256 * SROW) // 24576
#define SM_TOTAL (2 * STG_BYTES)     // 49152

template <int EPI>
__global__ void __launch_bounds__(512, 1)
k_tgemm(const float* __restrict__ A, const float* __restrict__ B,
        const float* __restrict__ bias, float* __restrict__ C, int M, int K)
{
    extern __shared__ char sm[];
    const uint32_t sb = smem_u32(sm);
    const int tid  = threadIdx.x;
    const int lane = tid & 31;
    const int wid  = tid >> 5;
    const int wm   = wid >> 2;      // 0..3  (M)
    const int wn   = wid & 3;       // 0..3  (N)
    const int bm   = blockIdx.x * BM;

    // fill mapping: each thread loads 4 consecutive k of one row
    const int arow = tid >> 2;          // 0..127
    const int aks  = (tid & 3) * 4;     // k offset 0/4/8/12
    const int brow0 = arow;             // B rows 0..127
    const int brow1 = 128 + arow;       // B rows 128..255

    // ldmatrix lane addresses (byte offsets within a stage)
    const uint32_t a_lrow = (uint32_t)(lane & 15);
    const uint32_t a_lkh  = (uint32_t)((lane >> 4) << 4);        // 0 or 16 bytes
    const uint32_t b_lrow = (uint32_t)((lane & 7) + ((lane >> 4) << 3));
    const uint32_t b_lkh  = (uint32_t)(((lane >> 3) & 1) << 4);

    float acc[2][8][4];
#pragma unroll
    for (int m = 0; m < 2; m++)
#pragma unroll
        for (int n = 0; n < 8; n++)
#pragma unroll
            for (int q = 0; q < 4; q++) acc[m][n][q] = 0.f;

    const int nt = (K + BK - 1) / BK;
    float fa[4], f0[4], f1[4];

    // prefetch stage 0
    {
        const int r = bm + arow;
        const float* Ap = A + (size_t)r * K + aks;
        const float* B0 = B + (size_t)brow0 * K + aks;
        const float* B1 = B + (size_t)brow1 * K + aks;
#pragma unroll
        for (int j = 0; j < 4; j++) {
            int k = aks + j;
            fa[j] = (r < M && k < K) ? __ldg(Ap + j) : 0.f;
            f0[j] = (k < K) ? __ldg(B0 + j) : 0.f;
            f1[j] = (k < K) ? __ldg(B1 + j) : 0.f;
        }
    }

    for (int kt = 0; kt < nt; kt++) {
        const uint32_t stg = (uint32_t)(kt & 1) * STG_BYTES;

        // ---- convert + store prefetched tile ----
        {
            uint2 hi, lo;
            cvt4a(fa, hi, lo);
            *(uint2*)(sm + stg + AH_OFF + arow * SROW + (tid & 3) * 8) = hi;
            *(uint2*)(sm + stg + AL_OFF + arow * SROW + (tid & 3) * 8) = lo;
            cvt4b(f0, hi);
            *(uint2*)(sm + stg + BH_OFF + brow0 * SROW + (tid & 3) * 8) = hi;
            cvt4b(f1, hi);
            *(uint2*)(sm + stg + BH_OFF + brow1 * SROW + (tid & 3) * 8) = hi;
        }
        __syncthreads();

        // ---- prefetch next stage into registers ----
        if (kt + 1 < nt) {
            const int k0 = (kt + 1) * BK;
            const int r = bm + arow;
            const float* Ap = A + (size_t)r * K + k0 + aks;
            const float* B0 = B + (size_t)brow0 * K + k0 + aks;
            const float* B1 = B + (size_t)brow1 * K + k0 + aks;
#pragma unroll
            for (int j = 0; j < 4; j++) {
                int k = k0 + aks + j;
                fa[j] = (r < M && k < K) ? __ldg(Ap + j) : 0.f;
                f0[j] = (k < K) ? __ldg(B0 + j) : 0.f;
                f1[j] = (k < K) ? __ldg(B1 + j) : 0.f;
            }
        }

        // ---- fragments + MMA ----
        uint32_t ah[2][4], al[2][4];
#pragma unroll
        for (int mt = 0; mt < 2; mt++) {
            uint32_t rowb = (uint32_t)(wm * 32 + mt * 16) + a_lrow;
            ldmx4(ah[mt], sb + stg + AH_OFF + rowb * SROW + a_lkh);
            ldmx4(al[mt], sb + stg + AL_OFF + rowb * SROW + a_lkh);
        }
#pragma unroll
        for (int ng = 0; ng < 4; ng++) {
            uint32_t bh[4];
            uint32_t nb = (uint32_t)(wn * 64 + ng * 16) + b_lrow;
            ldmx4(bh, sb + stg + BH_OFF + nb * SROW + b_lkh);
#pragma unroll
            for (int mt = 0; mt < 2; mt++) {
#pragma unroll
                for (int nf = 0; nf < 2; nf++) {
                    float* c = acc[mt][ng * 2 + nf];
                    mma_f16(c, ah[mt], &bh[nf * 2]);
                    mma_f16(c, al[mt], &bh[nf * 2]);
                }
            }
        }
    }

    // ---- epilogue ----
#pragma unroll
    for (int mt = 0; mt < 2; mt++) {
        int r0 = bm + wm * 32 + mt * 16 + (lane >> 2);
        int r1 = r0 + 8;
        float dv0 = 0.f, dv1 = 0.f;
        if (EPI == 0) {
            if (r0 < M) dv0 = g_dinv[r0];
            if (r1 < M) dv1 = g_dinv[r1];
        }
#pragma unroll
        for (int n = 0; n < 8; n++) {
            int col = wn * 64 + n * 8 + (lane & 3) * 2;
            float b0 = 0.f, b1 = 0.f;
            if (EPI != 0) { b0 = __ldg(bias + col); b1 = __ldg(bias + col + 1); }
            float* c = acc[mt][n];
            float v0 = c[0], v1 = c[1], v2 = c[2], v3 = c[3];
            if (EPI == 0) { v0 *= dv0; v1 *= dv0; v2 *= dv1; v3 *= dv1; }
            else {
                v0 += b0; v1 += b1; v2 += b0; v3 += b1;
                if (EPI == 1) {
                    v0 = (v0 > 0.f) ? v0 : expm1f(v0);
                    v1 = (v1 > 0.f) ? v1 : expm1f(v1);
                    v2 = (v2 > 0.f) ? v2 : expm1f(v2);
                    v3 = (v3 > 0.f) ? v3 : expm1f(v3);
                }
            }
            if (r0 < M) *(float2*)(C + (size_t)r0 * BN + col) = make_float2(v0, v1);
            if (r1 < M) *(float2*)(C + (size_t)r1 * BN + col) = make_float2(v2, v3);
        }
    }
}

// ============================ aggregation ============================
// out[v] = l2norm( relu( dinv[v]*(sum_{u->v} hs[u] + hs[v]) + bias ) )
__global__ void __launch_bounds__(HD)
k_agg(const float* __restrict__ hs, const float* __restrict__ bias,
      float* __restrict__ outx)
{
    int v = blockIdx.x;
    int j = threadIdx.x;

    float s = hs[(size_t)v * HD + j];
    int beg = g_rowptr[v], end = g_rowptr[v + 1];
#pragma unroll 4
    for (int e = beg; e < end; e++) {
        int u = __ldg(&g_srcs[e]);
        s += __ldg(&hs[(size_t)u * HD + j]);
    }
    float val = fmaf(g_dinv[v], s, bias[j]);
    val = fmaxf(val, 0.f);

    __shared__ float red[8];
    float ss = val * val;
#pragma unroll
    for (int o = 16; o; o >>= 1) ss += __shfl_xor_sync(0xffffffffu, ss, o);
    if ((j & 31) == 0) red[j >> 5] = ss;
    __syncthreads();
    if (j < 8) {
        float t = red[j];
#pragma unroll
        for (int o = 4; o; o >>= 1) t += __shfl_xor_sync(0xffu, t, o);
        if (j == 0) red[0] = t;
    }
    __syncthreads();
    float scale = 1.f / fmaxf(sqrtf(red[0]), 1e-12f);
    outx[(size_t)v * HD + j] = val * scale;
}

// ============================ launch ============================
extern "C" void kernel_launch(void* const* d_in, const int* in_sizes, int n_in,
                              void* d_out, int out_size)
{
    const float* x     = (const float*)d_in[0];
    const int*   edges = (const int*)  d_in[1];
    const float* Wg0   = (const float*)d_in[2];
    const float* bg0   = (const float*)d_in[3];
    const float* Wg1   = (const float*)d_in[4];
    const float* bg1   = (const float*)d_in[5];
    const float* Wg2   = (const float*)d_in[6];
    const float* bg2   = (const float*)d_in[7];
    const float* W1    = (const float*)d_in[8];
    const float* b1    = (const float*)d_in[9];
    const float* W2    = (const float*)d_in[10];
    const float* b2    = (const float*)d_in[11];
    float* out = (float*)d_out;

    const int* src = edges;
    const int* dst = edges + NE;

    float *hp, *xp;
    cudaGetSymbolAddress((void**)&hp, g_h);
    cudaGetSymbolAddress((void**)&xp, g_x);

    cudaFuncSetAttribute(k_tgemm<0>, cudaFuncAttributeMaxDynamicSharedMemorySize, SM_TOTAL);
    cudaFuncSetAttribute(k_tgemm<1>, cudaFuncAttributeMaxDynamicSharedMemorySize, SM_TOTAL);
    cudaFuncSetAttribute(k_tgemm<2>, cudaFuncAttributeMaxDynamicSharedMemorySize, SM_TOTAL);

    // CSR build + dinv
    k_zero   <<<(NN + 255) / 256, 256>>>();
    k_histo  <<<(NE + 255) / 256, 256>>>(dst);
    k_scan   <<<1, 1024>>>();
    k_scatter<<<(NE + 255) / 256, 256>>>(src, dst);

    const int grd = (NN + BM - 1) / BM;   // 391

    // GCN layer 0 (K = 2613)
    k_tgemm<0><<<grd, 512, SM_TOTAL>>>(x,  Wg0, nullptr, hp, NN, IND);
    k_agg     <<<NN, HD>>>(hp, bg0, xp);
    // GCN layer 1
    k_tgemm<0><<<grd, 512, SM_TOTAL>>>(xp, Wg1, nullptr, hp, NN, HD);
    k_agg     <<<NN, HD>>>(hp, bg1, xp);
    // GCN layer 2
    k_tgemm<0><<<grd, 512, SM_TOTAL>>>(xp, Wg2, nullptr, hp, NN, HD);
    k_agg     <<<NN, HD>>>(hp, bg2, xp);
    // MLP
    k_tgemm<1><<<grd, 512, SM_TOTAL>>>(xp, W1, b1, hp,  NN, HD);
    k_tgemm<2><<<grd, 512, SM_TOTAL>>>(hp, W2, b2, out, NN, HD);
}

// round 7
// speedup vs baseline: 1.5356x; 1.1704x over previous
#include <cuda_runtime.h>
#include <cuda_fp16.h>
#include <cstdint>

#define NN 50000
#define NE 800000
#define IND 2613
#define HD  256

// ---------------- scratch (static device memory; no allocs) ----------------
__device__ float g_h[(size_t)NN * HD];   // GEMM output h = X W^T
__device__ float g_x[(size_t)NN * HD];   // layer activations
__device__ float g_dinv[NN];
__device__ int   g_deg[NN];
__device__ int   g_cursor[NN];
__device__ int   g_rowptr[NN + 1];
__device__ int   g_srcs[NE];

// ============================ PTX helpers ============================
__device__ __forceinline__ uint32_t smem_u32(const void* p) {
    uint32_t a;
    asm("{ .reg .u64 t; cvta.to.shared.u64 t, %1; cvt.u32.u64 %0, t; }" : "=r"(a) : "l"(p));
    return a;
}
__device__ __forceinline__ void ldmx4(uint32_t* r, uint32_t addr) {
    asm volatile("ldmatrix.sync.aligned.m8n8.x4.shared.b16 {%0,%1,%2,%3}, [%4];"
                 : "=r"(r[0]), "=r"(r[1]), "=r"(r[2]), "=r"(r[3]) : "r"(addr));
}
__device__ __forceinline__ void mma_f16(float* c, const uint32_t* a, const uint32_t* b) {
    asm volatile("mma.sync.aligned.m16n8k16.row.col.f32.f16.f16.f32 "
                 "{%0,%1,%2,%3}, {%4,%5,%6,%7}, {%8,%9}, {%0,%1,%2,%3};"
                 : "+f"(c[0]), "+f"(c[1]), "+f"(c[2]), "+f"(c[3])
                 : "r"(a[0]), "r"(a[1]), "r"(a[2]), "r"(a[3]), "r"(b[0]), "r"(b[1]));
}

// ============================ CSR build ============================
__global__ void k_zero() {
    int i = blockIdx.x * blockDim.x + threadIdx.x;
    if (i < NN) { g_deg[i] = 0; g_cursor[i] = 0; }
}
__global__ void k_histo(const int* __restrict__ dst) {
    int e = blockIdx.x * blockDim.x + threadIdx.x;
    if (e < NE) atomicAdd(&g_deg[dst[e]], 1);
}
// single-block scan, thread-serial chunks + warp-shuffle block scan
#define SCH 49   // ceil(50000/1024)
__global__ void __launch_bounds__(1024) k_scan() {
    __shared__ int wsum[32];
    int tid = threadIdx.x;
    int lane = tid & 31, w = tid >> 5;
    int base = tid * SCH;

    int sum = 0;
    for (int j = 0; j < SCH; j++) {
        int i = base + j;
        int v = (i < NN) ? g_deg[i] : 0;
        if (i < NN) g_dinv[i] = rsqrtf((float)(v + 1));
        sum += v;
    }
    int x = sum;
#pragma unroll
    for (int o = 1; o < 32; o <<= 1) {
        int t = __shfl_up_sync(0xffffffffu, x, o);
        if (lane >= o) x += t;
    }
    if (lane == 31) wsum[w] = x;
    __syncthreads();
    if (w == 0) {
        int y = wsum[lane];
#pragma unroll
        for (int o = 1; o < 32; o <<= 1) {
            int t = __shfl_up_sync(0xffffffffu, y, o);
            if (lane >= o) y += t;
        }
        wsum[lane] = y;
    }
    __syncthreads();
    int excl = x - sum + (w > 0 ? wsum[w - 1] : 0);

    int run = excl;
    for (int j = 0; j < SCH; j++) {
        int i = base + j;
        if (i < NN) {
            g_rowptr[i] = run;
            run += g_deg[i];
        }
    }
    if (tid == 1023) g_rowptr[NN] = excl + sum;
}
__global__ void k_scatter(const int* __restrict__ src, const int* __restrict__ dst) {
    int e = blockIdx.x * blockDim.x + threadIdx.x;
    if (e < NE) {
        int d = dst[e];
        int p = g_rowptr[d] + atomicAdd(&g_cursor[d], 1);
        g_srcs[p] = src[e];
    }
}

// ============================ fp16 GEMM ============================
// C[i,j] = sum_k A[i,k]*B[j,k]; A:[M,K] fp32 row-major, B:[256,K] fp32 row-major.
// TERMS=1: acc += Ah*Bh (both rounded once, two-sided 2^-11 error)
// TERMS=2: acc += Ah*Bh + Al*Bh (A exact; one-sided B error)
// CTA: 128(M) x 256(N), 512 threads, 16 warps (4x4), warp tile 32x64.
// Coalesced fill: half-warp loads 16 consecutive floats of one row.
// EPI 0: C = acc ; EPI 1: elu(acc+bias) ; EPI 2: acc+bias
#define BM 128
#define BN 256
#define BK 16
#define SROW 48                      // bytes per smem row (16 fp16 + 16 pad)
#define AH_OFF 0
#define AL_OFF (128 * SROW)          // 6144
#define BH_OFF (2 * 128 * SROW)      // 12288
#define STG_BYTES (BH_OFF + 256 * SROW) // 24576
#define SM_TOTAL (2 * STG_BYTES)     // 49152

template <int EPI, int TERMS>
__global__ void __launch_bounds__(512, 1)
k_tgemm(const float* __restrict__ A, const float* __restrict__ B,
        const float* __restrict__ bias, float* __restrict__ C, int M, int K)
{
    extern __shared__ char sm[];
    const uint32_t sb = smem_u32(sm);
    const int tid  = threadIdx.x;
    const int lane = tid & 31;
    const int wid  = tid >> 5;
    const int wm   = wid >> 2;      // 0..3  (M)
    const int wn   = wid & 3;       // 0..3  (N)
    const int bm   = blockIdx.x * BM;

    // coalesced fill mapping: half-warp h loads cols 0..15 of one row
    const int half = lane >> 4;         // 0/1
    const int col  = lane & 15;         // 0..15

    // ldmatrix lane addresses (validated rounds 3/6)
    const uint32_t a_lrow = (uint32_t)(lane & 15);
    const uint32_t a_lkh  = (uint32_t)((lane >> 4) << 4);        // 0 or 16 bytes
    const uint32_t b_lrow = (uint32_t)((lane & 7) + ((lane >> 4) << 3));
    const uint32_t b_lkh  = (uint32_t)(((lane >> 3) & 1) << 4);

    float acc[2][8][4];
#pragma unroll
    for (int m = 0; m < 2; m++)
#pragma unroll
        for (int n = 0; n < 8; n++)
#pragma unroll
            for (int q = 0; q < 4; q++) acc[m][n][q] = 0.f;

    const int nt = (K + BK - 1) / BK;
    float fa[4], fb[8];

    // ---- prefetch one stage into registers (coalesced rows) ----
    auto prefetch = [&](int kt) {
        const int gk = kt * BK + col;
        const bool kin = gk < K;
#pragma unroll
        for (int i = 0; i < 4; i++) {
            int r  = wid * 8 + i * 2 + half;          // 0..127
            int gr = bm + r;
            fa[i] = (gr < M && kin) ? __ldg(A + (size_t)gr * K + gk) : 0.f;
        }
#pragma unroll
        for (int i = 0; i < 8; i++) {
            int r = wid * 16 + i * 2 + half;          // 0..255
            fb[i] = kin ? __ldg(B + (size_t)r * K + gk) : 0.f;
        }
    };

    prefetch(0);

    for (int kt = 0; kt < nt; kt++) {
        const uint32_t stg = (uint32_t)(kt & 1) * STG_BYTES;

        // ---- convert + store prefetched tile ----
#pragma unroll
        for (int i = 0; i < 4; i++) {
            int r = wid * 8 + i * 2 + half;
            __half hv = __float2half_rn(fa[i]);
            *(__half*)(sm + stg + AH_OFF + r * SROW + col * 2) = hv;
            if (TERMS == 2) {
                __half lv = __float2half_rn(fa[i] - __half2float(hv));
                *(__half*)(sm + stg + AL_OFF + r * SROW + col * 2) = lv;
            }
        }
#pragma unroll
        for (int i = 0; i < 8; i++) {
            int r = wid * 16 + i * 2 + half;
            *(__half*)(sm + stg + BH_OFF + r * SROW + col * 2) = __float2half_rn(fb[i]);
        }
        __syncthreads();

        if (kt + 1 < nt) prefetch(kt + 1);

        // ---- fragments + MMA ----
        uint32_t ah[2][4], al[2][4];
#pragma unroll
        for (int mt = 0; mt < 2; mt++) {
            uint32_t rowb = (uint32_t)(wm * 32 + mt * 16) + a_lrow;
            ldmx4(ah[mt], sb + stg + AH_OFF + rowb * SROW + a_lkh);
            if (TERMS == 2)
                ldmx4(al[mt], sb + stg + AL_OFF + rowb * SROW + a_lkh);
        }
#pragma unroll
        for (int ng = 0; ng < 4; ng++) {
            uint32_t bh[4];
            uint32_t nb = (uint32_t)(wn * 64 + ng * 16) + b_lrow;
            ldmx4(bh, sb + stg + BH_OFF + nb * SROW + b_lkh);
#pragma unroll
            for (int mt = 0; mt < 2; mt++) {
#pragma unroll
                for (int nf = 0; nf < 2; nf++) {
                    float* c = acc[mt][ng * 2 + nf];
                    mma_f16(c, ah[mt], &bh[nf * 2]);
                    if (TERMS == 2) mma_f16(c, al[mt], &bh[nf * 2]);
                }
            }
        }
    }

    // ---- epilogue ----
#pragma unroll
    for (int mt = 0; mt < 2; mt++) {
        int r0 = bm + wm * 32 + mt * 16 + (lane >> 2);
        int r1 = r0 + 8;
#pragma unroll
        for (int n = 0; n < 8; n++) {
            int cidx = wn * 64 + n * 8 + (lane & 3) * 2;
            float b0 = 0.f, b1 = 0.f;
            if (EPI != 0) { b0 = __ldg(bias + cidx); b1 = __ldg(bias + cidx + 1); }
            float* c = acc[mt][n];
            float v0 = c[0], v1 = c[1], v2 = c[2], v3 = c[3];
            if (EPI != 0) {
                v0 += b0; v1 += b1; v2 += b0; v3 += b1;
                if (EPI == 1) {
                    v0 = (v0 > 0.f) ? v0 : expm1f(v0);
                    v1 = (v1 > 0.f) ? v1 : expm1f(v1);
                    v2 = (v2 > 0.f) ? v2 : expm1f(v2);
                    v3 = (v3 > 0.f) ? v3 : expm1f(v3);
                }
            }
            if (r0 < M) *(float2*)(C + (size_t)r0 * BN + cidx) = make_float2(v0, v1);
            if (r1 < M) *(float2*)(C + (size_t)r1 * BN + cidx) = make_float2(v2, v3);
        }
    }
}

// ============================ aggregation ============================
// out[v] = l2norm( relu( dinv[v]*(sum_{u->v} h[u]*dinv[u] + h[v]*dinv[v]) + bias ) )
__global__ void __launch_bounds__(HD)
k_agg(const float* __restrict__ hs, const float* __restrict__ bias,
      float* __restrict__ outx)
{
    int v = blockIdx.x;
    int j = threadIdx.x;

    float dv = __ldg(&g_dinv[v]);
    float s = hs[(size_t)v * HD + j] * dv;
    int beg = g_rowptr[v], end = g_rowptr[v + 1];
#pragma unroll 4
    for (int e = beg; e < end; e++) {
        int u = __ldg(&g_srcs[e]);
        s += __ldg(&hs[(size_t)u * HD + j]) * __ldg(&g_dinv[u]);
    }
    float val = fmaf(dv, s, bias[j]);
    val = fmaxf(val, 0.f);

    __shared__ float red[8];
    float ss = val * val;
#pragma unroll
    for (int o = 16; o; o >>= 1) ss += __shfl_xor_sync(0xffffffffu, ss, o);
    if ((j & 31) == 0) red[j >> 5] = ss;
    __syncthreads();
    if (j < 8) {
        float t = red[j];
#pragma unroll
        for (int o = 4; o; o >>= 1) t += __shfl_xor_sync(0xffu, t, o);
        if (j == 0) red[0] = t;
    }
    __syncthreads();
    float scale = 1.f / fmaxf(sqrtf(red[0]), 1e-12f);
    outx[(size_t)v * HD + j] = val * scale;
}

// ============================ launch ============================
extern "C" void kernel_launch(void* const* d_in, const int* in_sizes, int n_in,
                              void* d_out, int out_size)
{
    const float* x     = (const float*)d_in[0];
    const int*   edges = (const int*)  d_in[1];
    const float* Wg0   = (const float*)d_in[2];
    const float* bg0   = (const float*)d_in[3];
    const float* Wg1   = (const float*)d_in[4];
    const float* bg1   = (const float*)d_in[5];
    const float* Wg2   = (const float*)d_in[6];
    const float* bg2   = (const float*)d_in[7];
    const float* W1    = (const float*)d_in[8];
    const float* b1    = (const float*)d_in[9];
    const float* W2    = (const float*)d_in[10];
    const float* b2    = (const float*)d_in[11];
    float* out = (float*)d_out;

    const int* src = edges;
    const int* dst = edges + NE;

    float *hp, *xp;
    cudaGetSymbolAddress((void**)&hp, g_h);
    cudaGetSymbolAddress((void**)&xp, g_x);

    cudaFuncSetAttribute((const void*)k_tgemm<0,1>, cudaFuncAttributeMaxDynamicSharedMemorySize, SM_TOTAL);
    cudaFuncSetAttribute((const void*)k_tgemm<1,2>, cudaFuncAttributeMaxDynamicSharedMemorySize, SM_TOTAL);
    cudaFuncSetAttribute((const void*)k_tgemm<2,2>, cudaFuncAttributeMaxDynamicSharedMemorySize, SM_TOTAL);

    // one-time side-stream + events (host objects, not device memory)
    static cudaStream_t s2 = nullptr;
    static cudaEvent_t evA = nullptr, evB = nullptr;
    if (s2 == nullptr) {
        cudaStreamCreateWithFlags(&s2, cudaStreamNonBlocking);
        cudaEventCreateWithFlags(&evA, cudaEventDisableTiming);
        cudaEventCreateWithFlags(&evB, cudaEventDisableTiming);
    }

    const int grd = (NN + BM - 1) / BM;   // 391

    // fork: CSR build on s2, GEMM0 on main stream (independent now)
    cudaEventRecord(evA, 0);
    cudaStreamWaitEvent(s2, evA, 0);
    k_zero   <<<(NN + 255) / 256, 256, 0, s2>>>();
    k_histo  <<<(NE + 255) / 256, 256, 0, s2>>>(dst);
    k_scan   <<<1, 1024, 0, s2>>>();
    k_scatter<<<(NE + 255) / 256, 256, 0, s2>>>(src, dst);
    cudaEventRecord(evB, s2);

    // GCN layer 0 (K = 2613) — no CSR dependency
    k_tgemm<0,1><<<grd, 512, SM_TOTAL>>>(x, Wg0, nullptr, hp, NN, IND);
    cudaStreamWaitEvent(0, evB, 0);            // join CSR before aggregation
    k_agg<<<NN, HD>>>(hp, bg0, xp);
    // GCN layer 1
    k_tgemm<0,1><<<grd, 512, SM_TOTAL>>>(xp, Wg1, nullptr, hp, NN, HD);
    k_agg<<<NN, HD>>>(hp, bg1, xp);
    // GCN layer 2
    k_tgemm<0,1><<<grd, 512, SM_TOTAL>>>(xp, Wg2, nullptr, hp, NN, HD);
    k_agg<<<NN, HD>>>(hp, bg2, xp);
    // MLP (2-term: errors hit output unnormalized)
    k_tgemm<1,2><<<grd, 512, SM_TOTAL>>>(xp, W1, b1, hp,  NN, HD);
    k_tgemm<2,2><<<grd, 512, SM_TOTAL>>>(hp, W2, b2, out, NN, HD);
}

// round 8
// speedup vs baseline: 1.9583x; 1.2753x over previous
#include <cuda_runtime.h>
#include <cuda_fp16.h>
#include <cstdint>

#define NN 50000
#define NE 800000
#define IND 2613
#define HD  256

// ---------------- scratch (static device memory; no allocs) ----------------
__device__ __half g_h16[(size_t)NN * HD];  // GEMM output h = X W^T (fp16)
__device__ __half g_x16[(size_t)NN * HD];  // layer activations (fp16)
__device__ float g_dinv[NN];
__device__ int   g_deg[NN];
__device__ int   g_cursor[NN];
__device__ int   g_rowptr[NN + 1];
__device__ int   g_srcs[NE];

// ============================ PTX helpers ============================
__device__ __forceinline__ uint32_t smem_u32(const void* p) {
    uint32_t a;
    asm("{ .reg .u64 t; cvta.to.shared.u64 t, %1; cvt.u32.u64 %0, t; }" : "=r"(a) : "l"(p));
    return a;
}
__device__ __forceinline__ void ldmx4(uint32_t* r, uint32_t addr) {
    asm volatile("ldmatrix.sync.aligned.m8n8.x4.shared.b16 {%0,%1,%2,%3}, [%4];"
                 : "=r"(r[0]), "=r"(r[1]), "=r"(r[2]), "=r"(r[3]) : "r"(addr));
}
__device__ __forceinline__ void mma_f16(float* c, const uint32_t* a, const uint32_t* b) {
    asm volatile("mma.sync.aligned.m16n8k16.row.col.f32.f16.f16.f32 "
                 "{%0,%1,%2,%3}, {%4,%5,%6,%7}, {%8,%9}, {%0,%1,%2,%3};"
                 : "+f"(c[0]), "+f"(c[1]), "+f"(c[2]), "+f"(c[3])
                 : "r"(a[0]), "r"(a[1]), "r"(a[2]), "r"(a[3]), "r"(b[0]), "r"(b[1]));
}

// ============================ CSR build ============================
__global__ void k_zero() {
    int i = blockIdx.x * blockDim.x + threadIdx.x;
    if (i < NN) { g_deg[i] = 0; g_cursor[i] = 0; }
}
__global__ void k_histo(const int* __restrict__ dst) {
    int e = blockIdx.x * blockDim.x + threadIdx.x;
    if (e < NE) atomicAdd(&g_deg[dst[e]], 1);
}
#define SCH 49   // ceil(50000/1024)
__global__ void __launch_bounds__(1024) k_scan() {
    __shared__ int wsum[32];
    int tid = threadIdx.x;
    int lane = tid & 31, w = tid >> 5;
    int base = tid * SCH;

    int sum = 0;
    for (int j = 0; j < SCH; j++) {
        int i = base + j;
        int v = (i < NN) ? g_deg[i] : 0;
        if (i < NN) g_dinv[i] = rsqrtf((float)(v + 1));
        sum += v;
    }
    int x = sum;
#pragma unroll
    for (int o = 1; o < 32; o <<= 1) {
        int t = __shfl_up_sync(0xffffffffu, x, o);
        if (lane >= o) x += t;
    }
    if (lane == 31) wsum[w] = x;
    __syncthreads();
    if (w == 0) {
        int y = wsum[lane];
#pragma unroll
        for (int o = 1; o < 32; o <<= 1) {
            int t = __shfl_up_sync(0xffffffffu, y, o);
            if (lane >= o) y += t;
        }
        wsum[lane] = y;
    }
    __syncthreads();
    int excl = x - sum + (w > 0 ? wsum[w - 1] : 0);

    int run = excl;
    for (int j = 0; j < SCH; j++) {
        int i = base + j;
        if (i < NN) {
            g_rowptr[i] = run;
            run += g_deg[i];
        }
    }
    if (tid == 1023) g_rowptr[NN] = excl + sum;
}
__global__ void k_scatter(const int* __restrict__ src, const int* __restrict__ dst) {
    int e = blockIdx.x * blockDim.x + threadIdx.x;
    if (e < NE) {
        int d = dst[e];
        int p = g_rowptr[d] + atomicAdd(&g_cursor[d], 1);
        g_srcs[p] = src[e];
    }
}

// ============================ fp16 GEMM ============================
// C[i,j] = sum_k A[i,k]*B[j,k]; A: [M,K] fp32 or fp16 row-major; B: [256,K] fp32.
// Single term: acc += Ah*Bh. When A is fp16 it is exact; fp32 A rounds once.
// CTA: 128(M) x 256(N), 512 threads, 16 warps (4x4), warp tile 32x64.
// EPI 0: C = acc ; EPI 1: elu(acc+bias) ; EPI 2: acc+bias
#define BM 128
#define BN 256
#define BK 16
#define SROW 48                       // bytes per smem row (16 fp16 + 16 pad)
#define AH_OFF 0
#define BH_OFF (128 * SROW)           // 6144
#define STG_BYTES (BH_OFF + 256 * SROW) // 18432
#define SM_TOTAL (2 * STG_BYTES)      // 36864

template <int EPI, bool AHALF, bool OUTH>
__global__ void __launch_bounds__(512, 1)
k_tgemm(const void* __restrict__ Av, const float* __restrict__ B,
        const float* __restrict__ bias, void* __restrict__ Cv, int M, int K)
{
    extern __shared__ char sm[];
    const uint32_t sb = smem_u32(sm);
    const int tid  = threadIdx.x;
    const int lane = tid & 31;
    const int wid  = tid >> 5;
    const int wm   = wid >> 2;      // 0..3  (M)
    const int wn   = wid & 3;       // 0..3  (N)
    const int bm   = blockIdx.x * BM;

    // coalesced fill mapping: half-warp loads cols 0..15 of one row
    const int half = lane >> 4;         // 0/1
    const int col  = lane & 15;         // 0..15

    const uint32_t a_lrow = (uint32_t)(lane & 15);
    const uint32_t a_lkh  = (uint32_t)((lane >> 4) << 4);
    const uint32_t b_lrow = (uint32_t)((lane & 7) + ((lane >> 4) << 3));
    const uint32_t b_lkh  = (uint32_t)(((lane >> 3) & 1) << 4);

    float acc[2][8][4];
#pragma unroll
    for (int m = 0; m < 2; m++)
#pragma unroll
        for (int n = 0; n < 8; n++)
#pragma unroll
            for (int q = 0; q < 4; q++) acc[m][n][q] = 0.f;

    const int nt = (K + BK - 1) / BK;
    float fa[4]; uint16_t ha[4]; float fb[8];

    auto prefetch = [&](int kt) {
        const int gk = kt * BK + col;
        const bool kin = gk < K;
#pragma unroll
        for (int i = 0; i < 4; i++) {
            int r  = wid * 8 + i * 2 + half;          // 0..127
            int gr = bm + r;
            bool in = (gr < M && kin);
            if (AHALF) {
                const uint16_t* Ap = (const uint16_t*)Av;
                ha[i] = in ? __ldg(Ap + (size_t)gr * K + gk) : (uint16_t)0;
            } else {
                const float* Ap = (const float*)Av;
                fa[i] = in ? __ldg(Ap + (size_t)gr * K + gk) : 0.f;
            }
        }
#pragma unroll
        for (int i = 0; i < 8; i++) {
            int r = wid * 16 + i * 2 + half;          // 0..255
            fb[i] = kin ? __ldg(B + (size_t)r * K + gk) : 0.f;
        }
    };

    prefetch(0);

    for (int kt = 0; kt < nt; kt++) {
        const uint32_t stg = (uint32_t)(kt & 1) * STG_BYTES;

        // ---- store prefetched tile ----
#pragma unroll
        for (int i = 0; i < 4; i++) {
            int r = wid * 8 + i * 2 + half;
            uint16_t hv;
            if (AHALF) hv = ha[i];
            else { __half h = __float2half_rn(fa[i]); hv = *(uint16_t*)&h; }
            *(uint16_t*)(sm + stg + AH_OFF + r * SROW + col * 2) = hv;
        }
#pragma unroll
        for (int i = 0; i < 8; i++) {
            int r = wid * 16 + i * 2 + half;
            *(__half*)(sm + stg + BH_OFF + r * SROW + col * 2) = __float2half_rn(fb[i]);
        }
        __syncthreads();

        if (kt + 1 < nt) prefetch(kt + 1);

        // ---- fragments + MMA ----
        uint32_t ah[2][4];
#pragma unroll
        for (int mt = 0; mt < 2; mt++) {
            uint32_t rowb = (uint32_t)(wm * 32 + mt * 16) + a_lrow;
            ldmx4(ah[mt], sb + stg + AH_OFF + rowb * SROW + a_lkh);
        }
#pragma unroll
        for (int ng = 0; ng < 4; ng++) {
            uint32_t bh[4];
            uint32_t nb = (uint32_t)(wn * 64 + ng * 16) + b_lrow;
            ldmx4(bh, sb + stg + BH_OFF + nb * SROW + b_lkh);
#pragma unroll
            for (int mt = 0; mt < 2; mt++) {
#pragma unroll
                for (int nf = 0; nf < 2; nf++)
                    mma_f16(acc[mt][ng * 2 + nf], ah[mt], &bh[nf * 2]);
            }
        }
    }

    // ---- epilogue ----
#pragma unroll
    for (int mt = 0; mt < 2; mt++) {
        int r0 = bm + wm * 32 + mt * 16 + (lane >> 2);
        int r1 = r0 + 8;
#pragma unroll
        for (int n = 0; n < 8; n++) {
            int cidx = wn * 64 + n * 8 + (lane & 3) * 2;
            float b0 = 0.f, b1 = 0.f;
            if (EPI != 0) { b0 = __ldg(bias + cidx); b1 = __ldg(bias + cidx + 1); }
            float* c = acc[mt][n];
            float v0 = c[0], v1 = c[1], v2 = c[2], v3 = c[3];
            if (EPI != 0) {
                v0 += b0; v1 += b1; v2 += b0; v3 += b1;
                if (EPI == 1) {
                    v0 = (v0 > 0.f) ? v0 : expm1f(v0);
                    v1 = (v1 > 0.f) ? v1 : expm1f(v1);
                    v2 = (v2 > 0.f) ? v2 : expm1f(v2);
                    v3 = (v3 > 0.f) ? v3 : expm1f(v3);
                }
            }
            if (OUTH) {
                __half* C = (__half*)Cv;
                if (r0 < M) *(__half2*)(C + (size_t)r0 * BN + cidx) = __floats2half2_rn(v0, v1);
                if (r1 < M) *(__half2*)(C + (size_t)r1 * BN + cidx) = __floats2half2_rn(v2, v3);
            } else {
                float* C = (float*)Cv;
                if (r0 < M) *(float2*)(C + (size_t)r0 * BN + cidx) = make_float2(v0, v1);
                if (r1 < M) *(float2*)(C + (size_t)r1 * BN + cidx) = make_float2(v2, v3);
            }
        }
    }
}

// ============================ aggregation (fp16 in/out) ============================
// out[v] = l2norm( relu( dinv[v]*(sum_{u->v} h[u]*dinv[u] + h[v]*dinv[v]) + bias ) )
// 128 threads/node; thread j owns dims 2j, 2j+1 (half2).
__global__ void __launch_bounds__(128)
k_agg(const __half* __restrict__ hs, const float* __restrict__ bias,
      __half* __restrict__ outx)
{
    int v = blockIdx.x;
    int j = threadIdx.x;
    const __half2* H = (const __half2*)hs;

    float dv = __ldg(&g_dinv[v]);
    float2 fself = __half22float2(H[(size_t)v * 128 + j]);
    float s0 = fself.x * dv, s1 = fself.y * dv;

    int beg = g_rowptr[v], end = g_rowptr[v + 1];
#pragma unroll 4
    for (int e = beg; e < end; e++) {
        int u = __ldg(&g_srcs[e]);
        float du = __ldg(&g_dinv[u]);
        float2 fu = __half22float2(H[(size_t)u * 128 + j]);
        s0 = fmaf(fu.x, du, s0);
        s1 = fmaf(fu.y, du, s1);
    }
    float2 bb = __ldg((const float2*)bias + j);
    float v0 = fmaxf(fmaf(dv, s0, bb.x), 0.f);
    float v1 = fmaxf(fmaf(dv, s1, bb.y), 0.f);

    __shared__ float red[4];
    float ss = v0 * v0 + v1 * v1;
#pragma unroll
    for (int o = 16; o; o >>= 1) ss += __shfl_xor_sync(0xffffffffu, ss, o);
    if ((j & 31) == 0) red[j >> 5] = ss;
    __syncthreads();
    if (j < 4) {
        float t = red[j];
#pragma unroll
        for (int o = 2; o; o >>= 1) t += __shfl_xor_sync(0xfu, t, o);
        if (j == 0) red[0] = t;
    }
    __syncthreads();
    float scale = 1.f / fmaxf(sqrtf(red[0]), 1e-12f);
    ((__half2*)outx)[(size_t)v * 128 + j] = __floats2half2_rn(v0 * scale, v1 * scale);
}

// ============================ launch ============================
extern "C" void kernel_launch(void* const* d_in, const int* in_sizes, int n_in,
                              void* d_out, int out_size)
{
    const float* x     = (const float*)d_in[0];
    const int*   edges = (const int*)  d_in[1];
    const float* Wg0   = (const float*)d_in[2];
    const float* bg0   = (const float*)d_in[3];
    const float* Wg1   = (const float*)d_in[4];
    const float* bg1   = (const float*)d_in[5];
    const float* Wg2   = (const float*)d_in[6];
    const float* bg2   = (const float*)d_in[7];
    const float* W1    = (const float*)d_in[8];
    const float* b1    = (const float*)d_in[9];
    const float* W2    = (const float*)d_in[10];
    const float* b2    = (const float*)d_in[11];
    float* out = (float*)d_out;

    const int* src = edges;
    const int* dst = edges + NE;

    __half *hp, *xp;
    cudaGetSymbolAddress((void**)&hp, g_h16);
    cudaGetSymbolAddress((void**)&xp, g_x16);

    cudaFuncSetAttribute((const void*)k_tgemm<0,false,true>, cudaFuncAttributeMaxDynamicSharedMemorySize, SM_TOTAL);
    cudaFuncSetAttribute((const void*)k_tgemm<0,true,true>,  cudaFuncAttributeMaxDynamicSharedMemorySize, SM_TOTAL);
    cudaFuncSetAttribute((const void*)k_tgemm<1,true,true>,  cudaFuncAttributeMaxDynamicSharedMemorySize, SM_TOTAL);
    cudaFuncSetAttribute((const void*)k_tgemm<2,true,false>, cudaFuncAttributeMaxDynamicSharedMemorySize, SM_TOTAL);

    static cudaStream_t s2 = nullptr;
    static cudaEvent_t evA = nullptr, evB = nullptr;
    if (s2 == nullptr) {
        cudaStreamCreateWithFlags(&s2, cudaStreamNonBlocking);
        cudaEventCreateWithFlags(&evA, cudaEventDisableTiming);
        cudaEventCreateWithFlags(&evB, cudaEventDisableTiming);
    }

    const int grd = (NN + BM - 1) / BM;   // 391

    // fork: CSR build on s2, GEMM0 on main stream
    cudaEventRecord(evA, 0);
    cudaStreamWaitEvent(s2, evA, 0);
    k_zero   <<<(NN + 255) / 256, 256, 0, s2>>>();
    k_histo  <<<(NE + 255) / 256, 256, 0, s2>>>(dst);
    k_scan   <<<1, 1024, 0, s2>>>();
    k_scatter<<<(NE + 255) / 256, 256, 0, s2>>>(src, dst);
    cudaEventRecord(evB, s2);

    // GCN layer 0 (K = 2613), fp32 A input
    k_tgemm<0,false,true><<<grd, 512, SM_TOTAL>>>(x, Wg0, nullptr, hp, NN, IND);
    cudaStreamWaitEvent(0, evB, 0);
    k_agg<<<NN, 128>>>(hp, bg0, xp);
    // GCN layer 1
    k_tgemm<0,true,true><<<grd, 512, SM_TOTAL>>>(xp, Wg1, nullptr, hp, NN, HD);
    k_agg<<<NN, 128>>>(hp, bg1, xp);
    // GCN layer 2
    k_tgemm<0,true,true><<<grd, 512, SM_TOTAL>>>(xp, Wg2, nullptr, hp, NN, HD);
    k_agg<<<NN, 128>>>(hp, bg2, xp);
    // MLP
    k_tgemm<1,true,true><<<grd, 512, SM_TOTAL>>>(xp, W1, b1, hp,  NN, HD);
    k_tgemm<2,true,false><<<grd, 512, SM_TOTAL>>>(hp, W2, b2, out, NN, HD);
}

// round 9
// speedup vs baseline: 2.1087x; 1.0768x over previous
#include <cuda_runtime.h>
#include <cuda_fp16.h>
#include <cstdint>

#define NN 50000
#define NE 800000
#define IND 2613
#define IND16 2624                    // IND padded to 16
#define HD  256

// ---------------- scratch (static device memory; no allocs) ----------------
__device__ __half g_h16[(size_t)NN * HD];  // GEMM output h = X W^T (fp16)
__device__ __half g_x16[(size_t)NN * HD];  // layer activations (fp16)
__device__ __half g_w16[256 * IND16 + 4 * 256 * 256]; // fp16 weights, padded rows
__device__ float g_dinv[NN];
__device__ int   g_deg[NN];
__device__ int   g_cursor[NN];
__device__ int   g_rowptr[NN + 1];
__device__ int   g_srcs[NE];

#define W0_OFF 0
#define W1_OFF (256 * IND16)
#define W2_OFF (W1_OFF + 256 * 256)
#define W3_OFF (W2_OFF + 256 * 256)
#define W4_OFF (W3_OFF + 256 * 256)

// ============================ PTX helpers ============================
__device__ __forceinline__ uint32_t smem_u32(const void* p) {
    uint32_t a;
    asm("{ .reg .u64 t; cvta.to.shared.u64 t, %1; cvt.u32.u64 %0, t; }" : "=r"(a) : "l"(p));
    return a;
}
__device__ __forceinline__ void ldmx4(uint32_t* r, uint32_t addr) {
    asm volatile("ldmatrix.sync.aligned.m8n8.x4.shared.b16 {%0,%1,%2,%3}, [%4];"
                 : "=r"(r[0]), "=r"(r[1]), "=r"(r[2]), "=r"(r[3]) : "r"(addr));
}
__device__ __forceinline__ void mma_f16(float* c, const uint32_t* a, const uint32_t* b) {
    asm volatile("mma.sync.aligned.m16n8k16.row.col.f32.f16.f16.f32 "
                 "{%0,%1,%2,%3}, {%4,%5,%6,%7}, {%8,%9}, {%0,%1,%2,%3};"
                 : "+f"(c[0]), "+f"(c[1]), "+f"(c[2]), "+f"(c[3])
                 : "r"(a[0]), "r"(a[1]), "r"(a[2]), "r"(a[3]), "r"(b[0]), "r"(b[1]));
}

// ============================ weight convert ============================
// out[r, 0..K16) = fp16(W[r, 0..K)), zero padded
__global__ void k_wcvt(const float* __restrict__ W, __half* __restrict__ out,
                       int K, int K16) {
    int i = blockIdx.x * 256 + threadIdx.x;
    if (i >= 256 * K16) return;
    int r = i / K16, c = i - r * K16;
    out[i] = (c < K) ? __float2half_rn(__ldg(W + (size_t)r * K + c)) : __half(0.f);
}

// ============================ CSR build ============================
__global__ void k_zero() {
    int i = blockIdx.x * blockDim.x + threadIdx.x;
    if (i < NN) { g_deg[i] = 0; g_cursor[i] = 0; }
}
__global__ void k_histo(const int* __restrict__ dst) {
    int e = blockIdx.x * blockDim.x + threadIdx.x;
    if (e < NE) atomicAdd(&g_deg[dst[e]], 1);
}
#define SCH 49   // ceil(50000/1024)
__global__ void __launch_bounds__(1024) k_scan() {
    __shared__ int wsum[32];
    int tid = threadIdx.x;
    int lane = tid & 31, w = tid >> 5;
    int base = tid * SCH;

    int sum = 0;
    for (int j = 0; j < SCH; j++) {
        int i = base + j;
        int v = (i < NN) ? g_deg[i] : 0;
        if (i < NN) g_dinv[i] = rsqrtf((float)(v + 1));
        sum += v;
    }
    int x = sum;
#pragma unroll
    for (int o = 1; o < 32; o <<= 1) {
        int t = __shfl_up_sync(0xffffffffu, x, o);
        if (lane >= o) x += t;
    }
    if (lane == 31) wsum[w] = x;
    __syncthreads();
    if (w == 0) {
        int y = wsum[lane];
#pragma unroll
        for (int o = 1; o < 32; o <<= 1) {
            int t = __shfl_up_sync(0xffffffffu, y, o);
            if (lane >= o) y += t;
        }
        wsum[lane] = y;
    }
    __syncthreads();
    int excl = x - sum + (w > 0 ? wsum[w - 1] : 0);

    int run = excl;
    for (int j = 0; j < SCH; j++) {
        int i = base + j;
        if (i < NN) {
            g_rowptr[i] = run;
            run += g_deg[i];
        }
    }
    if (tid == 1023) g_rowptr[NN] = excl + sum;
}
__global__ void k_scatter(const int* __restrict__ src, const int* __restrict__ dst) {
    int e = blockIdx.x * blockDim.x + threadIdx.x;
    if (e < NE) {
        int d = dst[e];
        int p = g_rowptr[d] + atomicAdd(&g_cursor[d], 1);
        g_srcs[p] = src[e];
    }
}

// ============================ fp16 GEMM ============================
// C[i,j] = sum_k A[i,k]*B16[j,k]; A: [M,K] fp32 or fp16; B16: [256,K16] fp16 padded.
// CTA: 128(M) x 256(N), 512 threads, 16 warps (4x4), warp tile 32x64.
// EPI 0: C = acc ; EPI 1: elu(acc+bias) ; EPI 2: acc+bias
#define BM 128
#define BN 256
#define BK 16
#define SROW 48                       // bytes per smem row (16 fp16 + 16 pad)
#define AH_OFF 0
#define BH_OFF (128 * SROW)           // 6144
#define STG_BYTES (BH_OFF + 256 * SROW) // 18432
#define SM_TOTAL (2 * STG_BYTES)      // 36864

template <int EPI, bool AHALF, bool OUTH>
__global__ void __launch_bounds__(512, 1)
k_tgemm(const void* __restrict__ Av, const __half* __restrict__ B16,
        const float* __restrict__ bias, void* __restrict__ Cv,
        int M, int K, int K16)
{
    extern __shared__ char sm[];
    const uint32_t sb = smem_u32(sm);
    const int tid  = threadIdx.x;
    const int lane = tid & 31;
    const int wid  = tid >> 5;
    const int wm   = wid >> 2;      // 0..3  (M)
    const int wn   = wid & 3;       // 0..3  (N)
    const int bm   = blockIdx.x * BM;

    // fill mappings (all vector-aligned)
    const int arow  = tid >> 2;          // 0..127
    const int acol  = (tid & 3) * 4;     // 0/4/8/12
    const int brow  = tid >> 1;          // 0..255
    const int bcolh = (tid & 1) * 8;     // 0/8

    const uint32_t a_lrow = (uint32_t)(lane & 15);
    const uint32_t a_lkh  = (uint32_t)((lane >> 4) << 4);
    const uint32_t b_lrow = (uint32_t)((lane & 7) + ((lane >> 4) << 3));
    const uint32_t b_lkh  = (uint32_t)(((lane >> 3) & 1) << 4);

    float acc[2][8][4];
#pragma unroll
    for (int m = 0; m < 2; m++)
#pragma unroll
        for (int n = 0; n < 8; n++)
#pragma unroll
            for (int q = 0; q < 4; q++) acc[m][n][q] = 0.f;

    const int nt = K16 / BK;
    uint2 va; float fa[4]; uint4 vb;

    auto prefetch = [&](int kt) {
        const int k0 = kt * BK;
        const int gr = bm + arow;
        if (AHALF) {
            const __half* Ap = (const __half*)Av;
            va = (gr < M) ? *(const uint2*)(Ap + (size_t)gr * K + k0 + acol)
                          : make_uint2(0u, 0u);
        } else {
            const float* Ap = (const float*)Av + (size_t)gr * K + k0 + acol;
#pragma unroll
            for (int j = 0; j < 4; j++) {
                int k = k0 + acol + j;
                fa[j] = (gr < M && k < K) ? __ldg(Ap + j) : 0.f;
            }
        }
        vb = *(const uint4*)(B16 + (size_t)brow * K16 + k0 + bcolh);
    };

    prefetch(0);

    for (int kt = 0; kt < nt; kt++) {
        const uint32_t stg = (uint32_t)(kt & 1) * STG_BYTES;

        // ---- store prefetched tile ----
        if (AHALF) {
            *(uint2*)(sm + stg + AH_OFF + arow * SROW + acol * 2) = va;
        } else {
            __half2 h0 = __floats2half2_rn(fa[0], fa[1]);
            __half2 h1 = __floats2half2_rn(fa[2], fa[3]);
            *(uint2*)(sm + stg + AH_OFF + arow * SROW + acol * 2) =
                make_uint2(*(uint32_t*)&h0, *(uint32_t*)&h1);
        }
        *(uint4*)(sm + stg + BH_OFF + brow * SROW + bcolh * 2) = vb;
        __syncthreads();

        if (kt + 1 < nt) prefetch(kt + 1);

        // ---- fragments + MMA ----
        uint32_t ah[2][4];
#pragma unroll
        for (int mt = 0; mt < 2; mt++) {
            uint32_t rowb = (uint32_t)(wm * 32 + mt * 16) + a_lrow;
            ldmx4(ah[mt], sb + stg + AH_OFF + rowb * SROW + a_lkh);
        }
#pragma unroll
        for (int ng = 0; ng < 4; ng++) {
            uint32_t bh[4];
            uint32_t nb = (uint32_t)(wn * 64 + ng * 16) + b_lrow;
            ldmx4(bh, sb + stg + BH_OFF + nb * SROW + b_lkh);
#pragma unroll
            for (int mt = 0; mt < 2; mt++) {
#pragma unroll
                for (int nf = 0; nf < 2; nf++)
                    mma_f16(acc[mt][ng * 2 + nf], ah[mt], &bh[nf * 2]);
            }
        }
    }

    // ---- epilogue ----
#pragma unroll
    for (int mt = 0; mt < 2; mt++) {
        int r0 = bm + wm * 32 + mt * 16 + (lane >> 2);
        int r1 = r0 + 8;
#pragma unroll
        for (int n = 0; n < 8; n++) {
            int cidx = wn * 64 + n * 8 + (lane & 3) * 2;
            float b0 = 0.f, b1 = 0.f;
            if (EPI != 0) { b0 = __ldg(bias + cidx); b1 = __ldg(bias + cidx + 1); }
            float* c = acc[mt][n];
            float v0 = c[0], v1 = c[1], v2 = c[2], v3 = c[3];
            if (EPI != 0) {
                v0 += b0; v1 += b1; v2 += b0; v3 += b1;
                if (EPI == 1) {
                    v0 = (v0 > 0.f) ? v0 : expm1f(v0);
                    v1 = (v1 > 0.f) ? v1 : expm1f(v1);
                    v2 = (v2 > 0.f) ? v2 : expm1f(v2);
                    v3 = (v3 > 0.f) ? v3 : expm1f(v3);
                }
            }
            if (OUTH) {
                __half* C = (__half*)Cv;
                if (r0 < M) *(__half2*)(C + (size_t)r0 * BN + cidx) = __floats2half2_rn(v0, v1);
                if (r1 < M) *(__half2*)(C + (size_t)r1 * BN + cidx) = __floats2half2_rn(v2, v3);
            } else {
                float* C = (float*)Cv;
                if (r0 < M) *(float2*)(C + (size_t)r0 * BN + cidx) = make_float2(v0, v1);
                if (r1 < M) *(float2*)(C + (size_t)r1 * BN + cidx) = make_float2(v2, v3);
            }
        }
    }
}

// ============================ aggregation (fp16 in/out) ============================
__global__ void __launch_bounds__(128)
k_agg(const __half* __restrict__ hs, const float* __restrict__ bias,
      __half* __restrict__ outx)
{
    int v = blockIdx.x;
    int j = threadIdx.x;
    const __half2* H = (const __half2*)hs;

    float dv = __ldg(&g_dinv[v]);
    float2 fself = __half22float2(H[(size_t)v * 128 + j]);
    float s0 = fself.x * dv, s1 = fself.y * dv;

    int beg = g_rowptr[v], end = g_rowptr[v + 1];
#pragma unroll 4
    for (int e = beg; e < end; e++) {
        int u = __ldg(&g_srcs[e]);
        float du = __ldg(&g_dinv[u]);
        float2 fu = __half22float2(H[(size_t)u * 128 + j]);
        s0 = fmaf(fu.x, du, s0);
        s1 = fmaf(fu.y, du, s1);
    }
    float2 bb = __ldg((const float2*)bias + j);
    float v0 = fmaxf(fmaf(dv, s0, bb.x), 0.f);
    float v1 = fmaxf(fmaf(dv, s1, bb.y), 0.f);

    __shared__ float red[4];
    float ss = v0 * v0 + v1 * v1;
#pragma unroll
    for (int o = 16; o; o >>= 1) ss += __shfl_xor_sync(0xffffffffu, ss, o);
    if ((j & 31) == 0) red[j >> 5] = ss;
    __syncthreads();
    if (j < 4) {
        float t = red[j];
#pragma unroll
        for (int o = 2; o; o >>= 1) t += __shfl_xor_sync(0xfu, t, o);
        if (j == 0) red[0] = t;
    }
    __syncthreads();
    float scale = 1.f / fmaxf(sqrtf(red[0]), 1e-12f);
    ((__half2*)outx)[(size_t)v * 128 + j] = __floats2half2_rn(v0 * scale, v1 * scale);
}

// ============================ launch ============================
extern "C" void kernel_launch(void* const* d_in, const int* in_sizes, int n_in,
                              void* d_out, int out_size)
{
    const float* x     = (const float*)d_in[0];
    const int*   edges = (const int*)  d_in[1];
    const float* Wg0   = (const float*)d_in[2];
    const float* bg0   = (const float*)d_in[3];
    const float* Wg1   = (const float*)d_in[4];
    const float* bg1   = (const float*)d_in[5];
    const float* Wg2   = (const float*)d_in[6];
    const float* bg2   = (const float*)d_in[7];
    const float* W1    = (const float*)d_in[8];
    const float* b1    = (const float*)d_in[9];
    const float* W2    = (const float*)d_in[10];
    const float* b2    = (const float*)d_in[11];
    float* out = (float*)d_out;

    const int* src = edges;
    const int* dst = edges + NE;

    __half *hp, *xp, *wp;
    cudaGetSymbolAddress((void**)&hp, g_h16);
    cudaGetSymbolAddress((void**)&xp, g_x16);
    cudaGetSymbolAddress((void**)&wp, g_w16);

    cudaFuncSetAttribute((const void*)k_tgemm<0,false,true>, cudaFuncAttributeMaxDynamicSharedMemorySize, SM_TOTAL);
    cudaFuncSetAttribute((const void*)k_tgemm<0,true,true>,  cudaFuncAttributeMaxDynamicSharedMemorySize, SM_TOTAL);
    cudaFuncSetAttribute((const void*)k_tgemm<1,true,true>,  cudaFuncAttributeMaxDynamicSharedMemorySize, SM_TOTAL);
    cudaFuncSetAttribute((const void*)k_tgemm<2,true,false>, cudaFuncAttributeMaxDynamicSharedMemorySize, SM_TOTAL);

    static cudaStream_t s2 = nullptr;
    static cudaEvent_t evA = nullptr, evB = nullptr;
    if (s2 == nullptr) {
        cudaStreamCreateWithFlags(&s2, cudaStreamNonBlocking);
        cudaEventCreateWithFlags(&evA, cudaEventDisableTiming);
        cudaEventCreateWithFlags(&evB, cudaEventDisableTiming);
    }

    const int grd = (NN + BM - 1) / BM;   // 391

    // fork: weight converts (small GEMM weights) + CSR on s2
    cudaEventRecord(evA, 0);
    cudaStreamWaitEvent(s2, evA, 0);
    k_wcvt<<<(256 * 256 + 255) / 256, 256, 0, s2>>>(Wg1, wp + W1_OFF, HD, HD);
    k_wcvt<<<(256 * 256 + 255) / 256, 256, 0, s2>>>(Wg2, wp + W2_OFF, HD, HD);
    k_wcvt<<<(256 * 256 + 255) / 256, 256, 0, s2>>>(W1,  wp + W3_OFF, HD, HD);
    k_wcvt<<<(256 * 256 + 255) / 256, 256, 0, s2>>>(W2,  wp + W4_OFF, HD, HD);
    k_zero   <<<(NN + 255) / 256, 256, 0, s2>>>();
    k_histo  <<<(NE + 255) / 256, 256, 0, s2>>>(dst);
    k_scan   <<<1, 1024, 0, s2>>>();
    k_scatter<<<(NE + 255) / 256, 256, 0, s2>>>(src, dst);
    cudaEventRecord(evB, s2);

    // main: Wg0 convert (needed by GEMM0), then GEMM0
    k_wcvt<<<(256 * IND16 + 255) / 256, 256>>>(Wg0, wp + W0_OFF, IND, IND16);
    k_tgemm<0,false,true><<<grd, 512, SM_TOTAL>>>(x, wp + W0_OFF, nullptr, hp, NN, IND, IND16);
    cudaStreamWaitEvent(0, evB, 0);
    k_agg<<<NN, 128>>>(hp, bg0, xp);
    // GCN layer 1
    k_tgemm<0,true,true><<<grd, 512, SM_TOTAL>>>(xp, wp + W1_OFF, nullptr, hp, NN, HD, HD);
    k_agg<<<NN, 128>>>(hp, bg1, xp);
    // GCN layer 2
    k_tgemm<0,true,true><<<grd, 512, SM_TOTAL>>>(xp, wp + W2_OFF, nullptr, hp, NN, HD, HD);
    k_agg<<<NN, 128>>>(hp, bg2, xp);
    // MLP
    k_tgemm<1,true,true><<<grd, 512, SM_TOTAL>>>(xp, wp + W3_OFF, b1, hp,  NN, HD, HD);
    k_tgemm<2,true,false><<<grd, 512, SM_TOTAL>>>(hp, wp + W4_OFF, b2, out, NN, HD, HD);
}

// round 10
// speedup vs baseline: 2.4211x; 1.1482x over previous
#include <cuda_runtime.h>
#include <cuda_fp16.h>
#include <cstdint>

#define NN 50000
#define NE 800000
#define IND 2613
#define IND16 2624                    // IND padded to 16
#define HD  256

// ---------------- scratch (static device memory; no allocs) ----------------
__device__ __half g_h16[(size_t)NN * HD];  // GEMM output h = X W^T (fp16)
__device__ __half g_x16[(size_t)NN * HD];  // layer activations (fp16)
__device__ __half g_w16[256 * IND16 + 4 * 256 * 256]; // fp16 weights, padded rows
__device__ float g_dinv[NN];
__device__ int   g_deg[NN];
__device__ int   g_cursor[NN];
__device__ int   g_rowptr[NN + 1];
__device__ int   g_srcs[NE];

#define W0_OFF 0
#define W1_OFF (256 * IND16)
#define W2_OFF (W1_OFF + 256 * 256)
#define W3_OFF (W2_OFF + 256 * 256)
#define W4_OFF (W3_OFF + 256 * 256)

// ============================ PTX helpers ============================
__device__ __forceinline__ uint32_t smem_u32(const void* p) {
    uint32_t a;
    asm("{ .reg .u64 t; cvta.to.shared.u64 t, %1; cvt.u32.u64 %0, t; }" : "=r"(a) : "l"(p));
    return a;
}
__device__ __forceinline__ void ldmx4(uint32_t* r, uint32_t addr) {
    asm volatile("ldmatrix.sync.aligned.m8n8.x4.shared.b16 {%0,%1,%2,%3}, [%4];"
                 : "=r"(r[0]), "=r"(r[1]), "=r"(r[2]), "=r"(r[3]) : "r"(addr));
}
__device__ __forceinline__ void mma_f16(float* c, const uint32_t* a, const uint32_t* b) {
    asm volatile("mma.sync.aligned.m16n8k16.row.col.f32.f16.f16.f32 "
                 "{%0,%1,%2,%3}, {%4,%5,%6,%7}, {%8,%9}, {%0,%1,%2,%3};"
                 : "+f"(c[0]), "+f"(c[1]), "+f"(c[2]), "+f"(c[3])
                 : "r"(a[0]), "r"(a[1]), "r"(a[2]), "r"(a[3]), "r"(b[0]), "r"(b[1]));
}

// ============================ weight convert ============================
__global__ void k_wcvt(const float* __restrict__ W, __half* __restrict__ out,
                       int K, int K16) {
    int i = blockIdx.x * 256 + threadIdx.x;
    if (i >= 256 * K16) return;
    int r = i / K16, c = i - r * K16;
    out[i] = (c < K) ? __float2half_rn(__ldg(W + (size_t)r * K + c)) : __half(0.f);
}

// ============================ CSR build ============================
__global__ void k_zero() {
    int i = blockIdx.x * blockDim.x + threadIdx.x;
    if (i < NN) { g_deg[i] = 0; g_cursor[i] = 0; }
}
__global__ void k_histo(const int* __restrict__ dst) {
    int e = blockIdx.x * blockDim.x + threadIdx.x;
    if (e < NE) atomicAdd(&g_deg[dst[e]], 1);
}
#define SCH 49   // ceil(50000/1024)
__global__ void __launch_bounds__(1024) k_scan() {
    __shared__ int wsum[32];
    int tid = threadIdx.x;
    int lane = tid & 31, w = tid >> 5;
    int base = tid * SCH;

    int sum = 0;
    for (int j = 0; j < SCH; j++) {
        int i = base + j;
        int v = (i < NN) ? g_deg[i] : 0;
        if (i < NN) g_dinv[i] = rsqrtf((float)(v + 1));
        sum += v;
    }
    int x = sum;
#pragma unroll
    for (int o = 1; o < 32; o <<= 1) {
        int t = __shfl_up_sync(0xffffffffu, x, o);
        if (lane >= o) x += t;
    }
    if (lane == 31) wsum[w] = x;
    __syncthreads();
    if (w == 0) {
        int y = wsum[lane];
#pragma unroll
        for (int o = 1; o < 32; o <<= 1) {
            int t = __shfl_up_sync(0xffffffffu, y, o);
            if (lane >= o) y += t;
        }
        wsum[lane] = y;
    }
    __syncthreads();
    int excl = x - sum + (w > 0 ? wsum[w - 1] : 0);

    int run = excl;
    for (int j = 0; j < SCH; j++) {
        int i = base + j;
        if (i < NN) {
            g_rowptr[i] = run;
            run += g_deg[i];
        }
    }
    if (tid == 1023) g_rowptr[NN] = excl + sum;
}
__global__ void k_scatter(const int* __restrict__ src, const int* __restrict__ dst) {
    int e = blockIdx.x * blockDim.x + threadIdx.x;
    if (e < NE) {
        int d = dst[e];
        int p = g_rowptr[d] + atomicAdd(&g_cursor[d], 1);
        g_srcs[p] = src[e];
    }
}

// ============================ fp16 GEMM ============================
// C[i,j] = sum_k A[i,k]*B16[j,k]; A: [M,K] fp32 or fp16; B16: [256,K16] fp16 padded.
// CTA: 128(M) x 128(N), 256 threads, 8 warps (4 M x 2 N), warp tile 32x64.
// 2 CTAs/SM for intra-SM fill/mma overlap. BK=32 (2 k-steps per stage).
// C is always [M, 256]; this CTA covers cols [bn, bn+128).
#define BM 128
#define BNT 128                       // N per CTA
#define BK 32
#define SROW 80                       // bytes per smem row (64 data + 16 pad)
#define A_OFF 0
#define B_OFF (128 * SROW)            // 10240
#define STG_BYTES (2 * 128 * SROW)    // 20480
#define SM_TOTAL (2 * STG_BYTES)      // 40960

template <int EPI, bool AHALF, bool OUTH>
__global__ void __launch_bounds__(256, 2)
k_tgemm(const void* __restrict__ Av, const __half* __restrict__ B16,
        const float* __restrict__ bias, void* __restrict__ Cv,
        int M, int K, int K16)
{
    extern __shared__ char sm[];
    const uint32_t sb = smem_u32(sm);
    const int tid  = threadIdx.x;
    const int lane = tid & 31;
    const int wid  = tid >> 5;
    const int wm   = wid >> 1;      // 0..3  (M, 32 rows each)
    const int wn   = wid & 1;       // 0..1  (N, 64 cols each)
    const int bm   = blockIdx.y * BM;
    const int bn   = blockIdx.x * BNT;

    // fill: 512 16B-chunks per matrix; thread handles chunks tid, tid+256
    // chunk -> row = id>>2, col16 = (id&3) (16B units within 64B row)
    const uint32_t a_lrow = (uint32_t)(lane & 15);
    const uint32_t a_lkh  = (uint32_t)((lane >> 4) << 4);
    const uint32_t b_lrow = (uint32_t)((lane & 7) + ((lane >> 4) << 3));
    const uint32_t b_lkh  = (uint32_t)(((lane >> 3) & 1) << 4);

    float acc[2][8][4];
#pragma unroll
    for (int m = 0; m < 2; m++)
#pragma unroll
        for (int n = 0; n < 8; n++)
#pragma unroll
            for (int q = 0; q < 4; q++) acc[m][n][q] = 0.f;

    const int nt = K16 / BK;
    uint4 va[2]; float fa[16]; uint4 vb[2];

    auto prefetch = [&](int kt) {
        const int k0 = kt * BK;
#pragma unroll
        for (int i = 0; i < 2; i++) {
            int id  = tid + i * 256;
            int row = id >> 2;
            int c8  = (id & 3) * 8;        // element offset within 32-col chunk
            int gr  = bm + row;
            if (AHALF) {
                const __half* Ap = (const __half*)Av;
                va[i] = (gr < M) ? *(const uint4*)(Ap + (size_t)gr * K + k0 + c8)
                                 : make_uint4(0u, 0u, 0u, 0u);
            } else {
                const float* Ap = (const float*)Av + (size_t)gr * K + k0 + c8;
#pragma unroll
                for (int j = 0; j < 8; j++) {
                    int k = k0 + c8 + j;
                    fa[i * 8 + j] = (gr < M && k < K) ? __ldg(Ap + j) : 0.f;
                }
            }
            int brw = bn + row;
            vb[i] = *(const uint4*)(B16 + (size_t)brw * K16 + k0 + c8);
        }
    };

    prefetch(0);

    for (int kt = 0; kt < nt; kt++) {
        const uint32_t stg = (uint32_t)(kt & 1) * STG_BYTES;

        // ---- store prefetched tile ----
#pragma unroll
        for (int i = 0; i < 2; i++) {
            int id  = tid + i * 256;
            int row = id >> 2;
            int cb  = (id & 3) * 16;       // byte offset within row
            if (AHALF) {
                *(uint4*)(sm + stg + A_OFF + row * SROW + cb) = va[i];
            } else {
                __half2 h0 = __floats2half2_rn(fa[i*8+0], fa[i*8+1]);
                __half2 h1 = __floats2half2_rn(fa[i*8+2], fa[i*8+3]);
                __half2 h2 = __floats2half2_rn(fa[i*8+4], fa[i*8+5]);
                __half2 h3 = __floats2half2_rn(fa[i*8+6], fa[i*8+7]);
                *(uint4*)(sm + stg + A_OFF + row * SROW + cb) =
                    make_uint4(*(uint32_t*)&h0, *(uint32_t*)&h1,
                               *(uint32_t*)&h2, *(uint32_t*)&h3);
            }
            *(uint4*)(sm + stg + B_OFF + row * SROW + cb) = vb[i];
        }
        __syncthreads();

        if (kt + 1 < nt) prefetch(kt + 1);

        // ---- fragments + MMA: 2 k-steps of 16 ----
#pragma unroll
        for (int s = 0; s < 2; s++) {
            uint32_t a[2][4];
#pragma unroll
            for (int mt = 0; mt < 2; mt++) {
                uint32_t rowb = (uint32_t)(wm * 32 + mt * 16) + a_lrow;
                ldmx4(a[mt], sb + stg + A_OFF + rowb * SROW + s * 32 + a_lkh);
            }
#pragma unroll
            for (int ng = 0; ng < 4; ng++) {
                uint32_t bh[4];
                uint32_t nb = (uint32_t)(wn * 64 + ng * 16) + b_lrow;
                ldmx4(bh, sb + stg + B_OFF + nb * SROW + s * 32 + b_lkh);
#pragma unroll
                for (int mt = 0; mt < 2; mt++) {
#pragma unroll
                    for (int nf = 0; nf < 2; nf++)
                        mma_f16(acc[mt][ng * 2 + nf], a[mt], &bh[nf * 2]);
                }
            }
        }
        __syncthreads();
    }

    // ---- epilogue (C row stride = 256 always) ----
#pragma unroll
    for (int mt = 0; mt < 2; mt++) {
        int r0 = bm + wm * 32 + mt * 16 + (lane >> 2);
        int r1 = r0 + 8;
#pragma unroll
        for (int n = 0; n < 8; n++) {
            int cidx = bn + wn * 64 + n * 8 + (lane & 3) * 2;
            float b0 = 0.f, b1 = 0.f;
            if (EPI != 0) { b0 = __ldg(bias + cidx); b1 = __ldg(bias + cidx + 1); }
            float* c = acc[mt][n];
            float v0 = c[0], v1 = c[1], v2 = c[2], v3 = c[3];
            if (EPI != 0) {
                v0 += b0; v1 += b1; v2 += b0; v3 += b1;
                if (EPI == 1) {
                    v0 = (v0 > 0.f) ? v0 : expm1f(v0);
                    v1 = (v1 > 0.f) ? v1 : expm1f(v1);
                    v2 = (v2 > 0.f) ? v2 : expm1f(v2);
                    v3 = (v3 > 0.f) ? v3 : expm1f(v3);
                }
            }
            if (OUTH) {
                __half* C = (__half*)Cv;
                if (r0 < M) *(__half2*)(C + (size_t)r0 * HD + cidx) = __floats2half2_rn(v0, v1);
                if (r1 < M) *(__half2*)(C + (size_t)r1 * HD + cidx) = __floats2half2_rn(v2, v3);
            } else {
                float* C = (float*)Cv;
                if (r0 < M) *(float2*)(C + (size_t)r0 * HD + cidx) = make_float2(v0, v1);
                if (r1 < M) *(float2*)(C + (size_t)r1 * HD + cidx) = make_float2(v2, v3);
            }
        }
    }
}

// ============================ aggregation (fp16 in/out) ============================
__global__ void __launch_bounds__(128)
k_agg(const __half* __restrict__ hs, const float* __restrict__ bias,
      __half* __restrict__ outx)
{
    int v = blockIdx.x;
    int j = threadIdx.x;
    const __half2* H = (const __half2*)hs;

    float dv = __ldg(&g_dinv[v]);
    float2 fself = __half22float2(H[(size_t)v * 128 + j]);
    float s0 = fself.x * dv, s1 = fself.y * dv;

    int beg = g_rowptr[v], end = g_rowptr[v + 1];
#pragma unroll 4
    for (int e = beg; e < end; e++) {
        int u = __ldg(&g_srcs[e]);
        float du = __ldg(&g_dinv[u]);
        float2 fu = __half22float2(H[(size_t)u * 128 + j]);
        s0 = fmaf(fu.x, du, s0);
        s1 = fmaf(fu.y, du, s1);
    }
    float2 bb = __ldg((const float2*)bias + j);
    float v0 = fmaxf(fmaf(dv, s0, bb.x), 0.f);
    float v1 = fmaxf(fmaf(dv, s1, bb.y), 0.f);

    __shared__ float red[4];
    float ss = v0 * v0 + v1 * v1;
#pragma unroll
    for (int o = 16; o; o >>= 1) ss += __shfl_xor_sync(0xffffffffu, ss, o);
    if ((j & 31) == 0) red[j >> 5] = ss;
    __syncthreads();
    if (j < 4) {
        float t = red[j];
#pragma unroll
        for (int o = 2; o; o >>= 1) t += __shfl_xor_sync(0xfu, t, o);
        if (j == 0) red[0] = t;
    }
    __syncthreads();
    float scale = 1.f / fmaxf(sqrtf(red[0]), 1e-12f);
    ((__half2*)outx)[(size_t)v * 128 + j] = __floats2half2_rn(v0 * scale, v1 * scale);
}

// ============================ launch ============================
extern "C" void kernel_launch(void* const* d_in, const int* in_sizes, int n_in,
                              void* d_out, int out_size)
{
    const float* x     = (const float*)d_in[0];
    const int*   edges = (const int*)  d_in[1];
    const float* Wg0   = (const float*)d_in[2];
    const float* bg0   = (const float*)d_in[3];
    const float* Wg1   = (const float*)d_in[4];
    const float* bg1   = (const float*)d_in[5];
    const float* Wg2   = (const float*)d_in[6];
    const float* bg2   = (const float*)d_in[7];
    const float* W1    = (const float*)d_in[8];
    const float* b1    = (const float*)d_in[9];
    const float* W2    = (const float*)d_in[10];
    const float* b2    = (const float*)d_in[11];
    float* out = (float*)d_out;

    const int* src = edges;
    const int* dst = edges + NE;

    __half *hp, *xp, *wp;
    cudaGetSymbolAddress((void**)&hp, g_h16);
    cudaGetSymbolAddress((void**)&xp, g_x16);
    cudaGetSymbolAddress((void**)&wp, g_w16);

    cudaFuncSetAttribute((const void*)k_tgemm<0,false,true>, cudaFuncAttributeMaxDynamicSharedMemorySize, SM_TOTAL);
    cudaFuncSetAttribute((const void*)k_tgemm<0,true,true>,  cudaFuncAttributeMaxDynamicSharedMemorySize, SM_TOTAL);
    cudaFuncSetAttribute((const void*)k_tgemm<1,true,true>,  cudaFuncAttributeMaxDynamicSharedMemorySize, SM_TOTAL);
    cudaFuncSetAttribute((const void*)k_tgemm<2,true,false>, cudaFuncAttributeMaxDynamicSharedMemorySize, SM_TOTAL);

    static cudaStream_t s2 = nullptr;
    static cudaEvent_t evA = nullptr, evB = nullptr;
    if (s2 == nullptr) {
        cudaStreamCreateWithFlags(&s2, cudaStreamNonBlocking);
        cudaEventCreateWithFlags(&evA, cudaEventDisableTiming);
        cudaEventCreateWithFlags(&evB, cudaEventDisableTiming);
    }

    const dim3 grd(2, (NN + BM - 1) / BM);   // (2, 391)

    cudaEventRecord(evA, 0);

    // main stream: wcvt W0/W1/W2, then GEMM0 as host-order launch #4 (ncu slot)
    k_wcvt<<<(256 * IND16 + 255) / 256, 256>>>(Wg0, wp + W0_OFF, IND, IND16);
    k_wcvt<<<(256 * 256 + 255) / 256, 256>>>(Wg1, wp + W1_OFF, HD, HD);
    k_wcvt<<<(256 * 256 + 255) / 256, 256>>>(Wg2, wp + W2_OFF, HD, HD);
    k_tgemm<0,false,true><<<grd, 256, SM_TOTAL>>>(x, wp + W0_OFF, nullptr, hp, NN, IND, IND16);

    // side stream: CSR + MLP weight converts (concurrent with GEMM0)
    cudaStreamWaitEvent(s2, evA, 0);
    k_zero   <<<(NN + 255) / 256, 256, 0, s2>>>();
    k_histo  <<<(NE + 255) / 256, 256, 0, s2>>>(dst);
    k_scan   <<<1, 1024, 0, s2>>>();
    k_scatter<<<(NE + 255) / 256, 256, 0, s2>>>(src, dst);
    k_wcvt<<<(256 * 256 + 255) / 256, 256, 0, s2>>>(W1, wp + W3_OFF, HD, HD);
    k_wcvt<<<(256 * 256 + 255) / 256, 256, 0, s2>>>(W2, wp + W4_OFF, HD, HD);
    cudaEventRecord(evB, s2);

    cudaStreamWaitEvent(0, evB, 0);
    k_agg<<<NN, 128>>>(hp, bg0, xp);
    // GCN layer 1
    k_tgemm<0,true,true><<<grd, 256, SM_TOTAL>>>(xp, wp + W1_OFF, nullptr, hp, NN, HD, HD);
    k_agg<<<NN, 128>>>(hp, bg1, xp);
    // GCN layer 2
    k_tgemm<0,true,true><<<grd, 256, SM_TOTAL>>>(xp, wp + W2_OFF, nullptr, hp, NN, HD, HD);
    k_agg<<<NN, 128>>>(hp, bg2, xp);
    // MLP
    k_tgemm<1,true,true><<<grd, 256, SM_TOTAL>>>(xp, wp + W3_OFF, b1, hp,  NN, HD, HD);
    k_tgemm<2,true,false><<<grd, 256, SM_TOTAL>>>(hp, wp + W4_OFF, b2, out, NN, HD, HD);
}